// round 4
// baseline (speedup 1.0000x reference)
#include <cuda_runtime.h>
#include <math.h>

// ---------------------------------------------------------------------------
// Problem constants
// ---------------------------------------------------------------------------
#define NA   256
#define HID  128
#define ACT  5
#define NH   4
#define DD   144
#define EE   576
#define HDH  144
#define OBS_RX 4
#define OBS_RY 2
#define WC_ROWS 145
#define NB   296          // persistent grid: exactly 2 CTAs per SM (148 SMs)

// ---------------------------------------------------------------------------
// Device scratch
// ---------------------------------------------------------------------------
__device__ float    g_C[NA * DD];
__device__ unsigned g_mask[NA * 8];
__device__ float    g_Wc [3][WC_ROWS * EE];   // K-split partial 0 (k 0..287)
__device__ float    g_Wc2[3][WC_ROWS * EE];   // K-split partial 1 (k 288..575)
__device__ float    g_Q[3][NA * EE];
__device__ float    g_S[NH * NA * NA];
__device__ float    g_G[NA * EE];
__device__ float    g_cnt[NA];
__device__ float    g_Wfin[EE * 6];
__device__ float    g_bfin[6];

// grid barrier (count returns to 0 per barrier; sense flips an even number of
// times per launch so state is identical across graph replays)
__device__ unsigned          g_bar_count;
__device__ volatile unsigned g_bar_sense;

// ---------------------------------------------------------------------------
// Shared memory union
// ---------------------------------------------------------------------------
struct SmemGemm  { float As[2][16][68]; float Bs[2][16][68]; };
struct SmemAttn  { float w[NH * NA]; int Jl[NA]; int sn; };
struct SmemHead  { float W2[EE * 6]; };
struct SmemSetup { int px[NA]; int py[NA]; };
union  SmemU { SmemGemm g; SmemAttn a; SmemHead h; SmemSetup s; };

// ---------------------------------------------------------------------------
__device__ __forceinline__ void mma16(const float (*As)[68], const float (*Bs)[68],
                                      int ty, int tx, float acc[4][4])
{
#pragma unroll
    for (int kk = 0; kk < 16; ++kk) {
        float a[4], b[4];
#pragma unroll
        for (int i = 0; i < 4; ++i) a[i] = As[kk][ty * 4 + i];
#pragma unroll
        for (int j = 0; j < 4; ++j) b[j] = Bs[kk][tx * 4 + j];
#pragma unroll
        for (int i = 0; i < 4; ++i)
#pragma unroll
            for (int j = 0; j < 4; ++j) acc[i][j] += a[i] * b[j];
    }
}

#define GRID_BAR()                                                        \
    do {                                                                  \
        __threadfence();                                                  \
        __syncthreads();                                                  \
        if (tid == 0) {                                                   \
            unsigned target = s_sense ^ 1u;                               \
            s_sense = target;                                             \
            unsigned aidx = atomicAdd(&g_bar_count, 1u);                  \
            if (aidx == (unsigned)(NB - 1)) {                             \
                g_bar_count = 0u;                                         \
                __threadfence();                                          \
                g_bar_sense = target;                                     \
            } else {                                                      \
                while (g_bar_sense != target) __nanosleep(64);            \
            }                                                             \
        }                                                                 \
        __syncthreads();                                                  \
    } while (0)

// ---------------------------------------------------------------------------
__global__ __launch_bounds__(256, 2)
void fused_kernel(const float* __restrict__ hid,   const float* __restrict__ act,
                  const int*   __restrict__ state,
                  const float* __restrict__ W_enc, const float* __restrict__ b_enc,
                  const float* __restrict__ Wq,  const float* __restrict__ bq,
                  const float* __restrict__ Wk,  const float* __restrict__ bk,
                  const float* __restrict__ Wv,  const float* __restrict__ bv,
                  const float* __restrict__ Wiq, const float* __restrict__ biq,
                  const float* __restrict__ Wik, const float* __restrict__ bik,
                  const float* __restrict__ Wiv, const float* __restrict__ biv,
                  const float* __restrict__ Wo,  const float* __restrict__ bo,
                  const float* __restrict__ W_O,
                  const float* __restrict__ W_val, const float* __restrict__ b_val,
                  const float* __restrict__ W_adv, const float* __restrict__ b_adv,
                  float* __restrict__ out)
{
    __shared__ SmemU sm;
    __shared__ unsigned s_sense;
    const int tid = threadIdx.x;
    const int bx  = blockIdx.x;
    if (tid == 0) s_sense = 0u;

    const int tx  = tid & 15;
    const int ty  = tid >> 4;
    const int ma  = tid >> 2;
    const int ka  = (tid & 3) * 4;
    const int kb  = tid >> 4;
    const int nbv = (tid & 15) * 4;

    // =====================================================================
    // STAGE A (parallel tasks):
    //   bx   0..161 : combined proj weights, K-split in 2 partial buffers
    //   bx 162..170 : head combine (Wfin, bfin)
    //   bx 171..178 : obs encoder + action copy -> g_C
    //   bx  == 179  : visibility mask
    // =====================================================================
    if (bx < 162) {
        const int z    = bx / 54;
        const int r    = bx % 54;
        const int tile = r >> 1;
        const int ks   = r & 1;
        const int m0   = (tile / 9) * 64, n0 = (tile % 9) * 64;
        const int kbase = ks * 288;

        const float* Az   = (z == 0) ? Wq  : (z == 1) ? Wk  : Wv;
        const float* brow = (z == 0) ? bq  : (z == 1) ? bk  : bv;
        const float* Bz   = (z == 0) ? Wiq : (z == 1) ? Wik : Wiv;
        const float* bi   = (z == 0) ? biq : (z == 1) ? bik : biv;
        float* Cd = ks ? &g_Wc2[z][0] : &g_Wc[z][0];

        // branch-free A-row pointer (row 0..143 -> Wz row, 144 -> bias row,
        // >144 -> null = zero fill)
        const int rA = m0 + ma;
        const float* arp = (rA < DD) ? (Az + rA * EE) : ((rA == DD) ? brow : nullptr);

        float acc[4][4] = {};
        float4 va, vb;
        va = arp ? *(const float4*)&arp[kbase + ka] : make_float4(0.f, 0.f, 0.f, 0.f);
        vb = *(const float4*)&Bz[(kbase + kb) * EE + n0 + nbv];
        sm.g.As[0][ka + 0][ma] = va.x; sm.g.As[0][ka + 1][ma] = va.y;
        sm.g.As[0][ka + 2][ma] = va.z; sm.g.As[0][ka + 3][ma] = va.w;
        sm.g.Bs[0][kb][nbv + 0] = vb.x; sm.g.Bs[0][kb][nbv + 1] = vb.y;
        sm.g.Bs[0][kb][nbv + 2] = vb.z; sm.g.Bs[0][kb][nbv + 3] = vb.w;
        __syncthreads();

        const int nk = 288 / 16;   // 18
        for (int it = 0; it < nk; ++it) {
            const int buf = it & 1;
            if (it + 1 < nk) {
                const int k0 = kbase + (it + 1) * 16;
                va = arp ? *(const float4*)&arp[k0 + ka] : make_float4(0.f, 0.f, 0.f, 0.f);
                vb = *(const float4*)&Bz[(k0 + kb) * EE + n0 + nbv];
            }
            mma16(sm.g.As[buf], sm.g.Bs[buf], ty, tx, acc);
            if (it + 1 < nk) {
                const int nb2 = buf ^ 1;
                sm.g.As[nb2][ka + 0][ma] = va.x; sm.g.As[nb2][ka + 1][ma] = va.y;
                sm.g.As[nb2][ka + 2][ma] = va.z; sm.g.As[nb2][ka + 3][ma] = va.w;
                sm.g.Bs[nb2][kb][nbv + 0] = vb.x; sm.g.Bs[nb2][kb][nbv + 1] = vb.y;
                sm.g.Bs[nb2][kb][nbv + 2] = vb.z; sm.g.Bs[nb2][kb][nbv + 3] = vb.w;
            }
            __syncthreads();
        }
#pragma unroll
        for (int i = 0; i < 4; ++i) {
            const int m = m0 + ty * 4 + i;
            if (m >= WC_ROWS) continue;
#pragma unroll
            for (int j = 0; j < 4; ++j) {
                const int n = n0 + tx * 4 + j;
                float v = acc[i][j];
                if (ks == 0 && m == DD) v += bi[n];   // inner bias once
                Cd[m * EE + n] = v;
            }
        }
    } else if (bx < 171) {
        // ---- head combine ----
        for (int r = tid; r < EE; r += 256) {
            float a[6] = {};
            for (int k = 0; k < DD; ++k) {
                const float w = W_O[r * DD + k];
                a[0] += w * W_val[k];
#pragma unroll
                for (int j = 0; j < ACT; ++j) a[1 + j] += w * W_adv[k * ACT + j];
            }
#pragma unroll
            for (int j = 0; j < 6; ++j) sm.h.W2[r * 6 + j] = a[j];
        }
        __syncthreads();
        if (tid < 64) {
            const int e = (bx - 162) * 64 + tid;
            float a[6] = {};
            for (int f = 0; f < EE; ++f) {
                const float w = Wo[e * EE + f];
#pragma unroll
                for (int j = 0; j < 6; ++j) a[j] += w * sm.h.W2[f * 6 + j];
            }
#pragma unroll
            for (int j = 0; j < 6; ++j) g_Wfin[e * 6 + j] = a[j];
        } else if (bx == 162 && tid < 70) {
            const int j = tid - 64;
            float s = 0.f;
            for (int f = 0; f < EE; ++f) s += bo[f] * sm.h.W2[f * 6 + j];
            g_bfin[j] = s;
        }
    } else if (bx < 179) {
        // ---- obs encoder (32 agents per block) + action copy ----
        const int base = (bx - 171) * 32;
        const int ai   = base + (tid >> 3);
        const int tgrp = (tid & 7) * 2;
        float o0 = b_enc[tgrp], o1 = b_enc[tgrp + 1];
        for (int d = 0; d < HID; ++d) {
            const float hv = hid[ai * HID + d];
            o0 += hv * W_enc[d * 16 + tgrp];
            o1 += hv * W_enc[d * 16 + tgrp + 1];
        }
        g_C[ai * DD + tgrp]     = o0;
        g_C[ai * DD + tgrp + 1] = o1;
        const float4* act4 = (const float4*)act;
        for (int idx = tid; idx < 32 * 32; idx += 256) {
            const int row = idx >> 5, col = idx & 31;
            *(float4*)&g_C[(base + row) * DD + 16 + col * 4] =
                act4[(base + row) * 32 + col];
        }
    } else if (bx == 179) {
        // ---- visibility mask ----
        const int i = tid;
        sm.s.px[i] = state[2 * i];
        sm.s.py[i] = state[2 * i + 1];
        __syncthreads();
        unsigned wbits[8] = {0, 0, 0, 0, 0, 0, 0, 0};
        const int xi = sm.s.px[i], yi = sm.s.py[i];
        for (int j = i + 1; j < NA; ++j) {
            const int dx = abs(xi - sm.s.px[j]);
            const int dy = abs(yi - sm.s.py[j]);
            if (dx <= OBS_RX && dy <= OBS_RY) wbits[j >> 5] |= (1u << (j & 31));
        }
#pragma unroll
        for (int t = 0; t < 8; ++t) g_mask[i * 8 + t] = wbits[t];
    }
    GRID_BAR();

    // =====================================================================
    // STAGE B: q,k,v = C @ (Wc + Wc2) + bias-row    (108 tiles)
    // =====================================================================
    if (bx < 108) {
        const int z  = bx / 36, r = bx % 36;
        const int m0 = (r / 9) * 64, n0 = (r % 9) * 64;
        const float* B0 = &g_Wc [z][0];
        const float* B1 = &g_Wc2[z][0];
        float* Cd = &g_Q[z][0];

        float acc[4][4] = {};
        float4 va, vb0, vb1;
        va  = *(const float4*)&g_C[(m0 + ma) * DD + ka];
        vb0 = *(const float4*)&B0[kb * EE + n0 + nbv];
        vb1 = *(const float4*)&B1[kb * EE + n0 + nbv];
        sm.g.As[0][ka + 0][ma] = va.x; sm.g.As[0][ka + 1][ma] = va.y;
        sm.g.As[0][ka + 2][ma] = va.z; sm.g.As[0][ka + 3][ma] = va.w;
        sm.g.Bs[0][kb][nbv + 0] = vb0.x + vb1.x; sm.g.Bs[0][kb][nbv + 1] = vb0.y + vb1.y;
        sm.g.Bs[0][kb][nbv + 2] = vb0.z + vb1.z; sm.g.Bs[0][kb][nbv + 3] = vb0.w + vb1.w;
        __syncthreads();

        const int nk = DD / 16;   // 9
        for (int it = 0; it < nk; ++it) {
            const int buf = it & 1;
            if (it + 1 < nk) {
                const int k0 = (it + 1) * 16;
                va  = *(const float4*)&g_C[(m0 + ma) * DD + k0 + ka];
                vb0 = *(const float4*)&B0[(k0 + kb) * EE + n0 + nbv];
                vb1 = *(const float4*)&B1[(k0 + kb) * EE + n0 + nbv];
            }
            mma16(sm.g.As[buf], sm.g.Bs[buf], ty, tx, acc);
            if (it + 1 < nk) {
                const int nb2 = buf ^ 1;
                sm.g.As[nb2][ka + 0][ma] = va.x; sm.g.As[nb2][ka + 1][ma] = va.y;
                sm.g.As[nb2][ka + 2][ma] = va.z; sm.g.As[nb2][ka + 3][ma] = va.w;
                sm.g.Bs[nb2][kb][nbv + 0] = vb0.x + vb1.x; sm.g.Bs[nb2][kb][nbv + 1] = vb0.y + vb1.y;
                sm.g.Bs[nb2][kb][nbv + 2] = vb0.z + vb1.z; sm.g.Bs[nb2][kb][nbv + 3] = vb0.w + vb1.w;
            }
            __syncthreads();
        }
#pragma unroll
        for (int i = 0; i < 4; ++i) {
            const int m = m0 + ty * 4 + i;
#pragma unroll
            for (int j = 0; j < 4; ++j) {
                const int n = n0 + tx * 4 + j;
                const float bias = B0[DD * EE + n] + B1[DD * EE + n];
                Cd[m * EE + n] = acc[i][j] + bias;
            }
        }
    }
    GRID_BAR();

    // =====================================================================
    // STAGE C: S[h] = scale * q2_h @ k2_h^T   (64 tiles)
    // =====================================================================
    if (bx < 64) {
        const int h  = bx >> 4;
        const int m0 = ((bx >> 2) & 3) * 64;
        const int n0 = (bx & 3) * 64;
        const float* A = &g_Q[0][0] + h * HDH;
        const float* B = &g_Q[1][0] + h * HDH;
        float* Cd = g_S + h * NA * NA;
        const float scale = 1.0f / 12.0f;

        float acc[4][4] = {};
        float4 va, vb;
        va = *(const float4*)&A[(m0 + ma) * EE + ka];
        vb = *(const float4*)&B[(n0 + ma) * EE + ka];
        sm.g.As[0][ka + 0][ma] = va.x; sm.g.As[0][ka + 1][ma] = va.y;
        sm.g.As[0][ka + 2][ma] = va.z; sm.g.As[0][ka + 3][ma] = va.w;
        sm.g.Bs[0][ka + 0][ma] = vb.x; sm.g.Bs[0][ka + 1][ma] = vb.y;
        sm.g.Bs[0][ka + 2][ma] = vb.z; sm.g.Bs[0][ka + 3][ma] = vb.w;
        __syncthreads();

        const int nk = HDH / 16;   // 9
        for (int it = 0; it < nk; ++it) {
            const int buf = it & 1;
            if (it + 1 < nk) {
                const int k0 = (it + 1) * 16;
                va = *(const float4*)&A[(m0 + ma) * EE + k0 + ka];
                vb = *(const float4*)&B[(n0 + ma) * EE + k0 + ka];
            }
            mma16(sm.g.As[buf], sm.g.Bs[buf], ty, tx, acc);
            if (it + 1 < nk) {
                const int nb2 = buf ^ 1;
                sm.g.As[nb2][ka + 0][ma] = va.x; sm.g.As[nb2][ka + 1][ma] = va.y;
                sm.g.As[nb2][ka + 2][ma] = va.z; sm.g.As[nb2][ka + 3][ma] = va.w;
                sm.g.Bs[nb2][ka + 0][ma] = vb.x; sm.g.Bs[nb2][ka + 1][ma] = vb.y;
                sm.g.Bs[nb2][ka + 2][ma] = vb.z; sm.g.Bs[nb2][ka + 3][ma] = vb.w;
            }
            __syncthreads();
        }
#pragma unroll
        for (int i = 0; i < 4; ++i) {
            const int m = m0 + ty * 4 + i;
#pragma unroll
            for (int j = 0; j < 4; ++j) {
                const int n = n0 + tx * 4 + j;
                Cd[m * NA + n] = scale * acc[i][j];
            }
        }
    }
    GRID_BAR();

    // =====================================================================
    // STAGE D: per-agent masked softmax-sum + sparse context -> G, cnt
    // =====================================================================
    if (bx < NA) {
        const int i = bx;
        for (int t = tid; t < NH * NA; t += 256) sm.a.w[t] = 0.f;
        if (tid == 0) {
            int n = 0;
            for (int t = 0; t < 8; ++t) {
                unsigned bits = g_mask[i * 8 + t];
                while (bits) {
                    const int b = __ffs(bits) - 1;
                    sm.a.Jl[n++] = t * 32 + b;
                    bits &= bits - 1;
                }
            }
            sm.a.sn = n;
            g_cnt[i] = (float)n;
        }
        __syncthreads();

        const int n = sm.a.sn;
        if (n == 0) {
            for (int e = tid; e < EE; e += 256) g_G[i * EE + e] = 0.f;
        } else {
            for (int p = tid; p < NH * n; p += 256) {
                const int h  = p & 3;
                const int jj = sm.a.Jl[p >> 2];
                const float* row = g_S + h * NA * NA + jj * NA;
                float m = -1e30f;
                for (int t = 0; t < n; ++t) m = fmaxf(m, row[sm.a.Jl[t]]);
                float sum = 0.f;
                for (int t = 0; t < n; ++t) sum += expf(row[sm.a.Jl[t]] - m);
                const float inv = 1.f / sum;
                for (int t = 0; t < n; ++t)
                    atomicAdd(&sm.a.w[h * NA + t], expf(row[sm.a.Jl[t]] - m) * inv);
            }
            __syncthreads();
            const float* v2 = &g_Q[2][0];
            for (int e = tid; e < EE; e += 256) {
                const int h = e / HDH;
                float acc = 0.f;
                for (int t = 0; t < n; ++t)
                    acc += sm.a.w[h * NA + t] * v2[sm.a.Jl[t] * EE + e];
                g_G[i * EE + e] = acc;
            }
        }
    }
    GRID_BAR();

    // =====================================================================
    // STAGE E: warp-per-agent final head (32 blocks x 8 warps)
    // =====================================================================
    {
        const int gw   = bx * 8 + (tid >> 5);
        const int lane = tid & 31;
        if (gw < NA) {
            const float* Gr = g_G + gw * EE;
            float a[6] = {};
            for (int d = lane; d < EE; d += 32) {
                const float gv = Gr[d];
                const float* Wr = g_Wfin + d * 6;
#pragma unroll
                for (int j = 0; j < 6; ++j) a[j] += gv * Wr[j];
            }
#pragma unroll
            for (int j = 0; j < 6; ++j)
#pragma unroll
                for (int o = 16; o > 0; o >>= 1)
                    a[j] += __shfl_xor_sync(0xffffffffu, a[j], o);
            const float c = g_cnt[gw];
            const float V = a[0] + c * g_bfin[0] + b_val[0];
            float A[ACT], mean = 0.f;
#pragma unroll
            for (int j = 0; j < ACT; ++j) {
                A[j] = a[1 + j] + c * g_bfin[1 + j] + b_adv[j];
                mean += A[j];
            }
            mean *= (1.f / ACT);
            if (lane < ACT) out[gw * ACT + lane] = V + A[lane] - mean;
        }
    }
}

// ---------------------------------------------------------------------------
// Launch
// ---------------------------------------------------------------------------
extern "C" void kernel_launch(void* const* d_in, const int* in_sizes, int n_in,
                              void* d_out, int out_size)
{
    const float *hid, *act, *W_enc, *b_enc, *Wq, *bq, *Wk, *bk, *Wv, *bv;
    const float *Wiq, *biq, *Wik, *bik, *Wiv, *biv, *Wo, *bo, *W_O;
    const float *W_val, *b_val, *W_adv, *b_adv;
    const int* state;

    if (n_in >= 3 && in_sizes[2] == 512) {
        hid   = (const float*)d_in[0];  act  = (const float*)d_in[1];
        state = (const int*)  d_in[2];
        W_enc = (const float*)d_in[3];  b_enc = (const float*)d_in[4];
        Wq  = (const float*)d_in[5];    bq  = (const float*)d_in[6];
        Wk  = (const float*)d_in[7];    bk  = (const float*)d_in[8];
        Wv  = (const float*)d_in[9];    bv  = (const float*)d_in[10];
        Wiq = (const float*)d_in[11];   biq = (const float*)d_in[12];
        Wik = (const float*)d_in[13];   bik = (const float*)d_in[14];
        Wiv = (const float*)d_in[15];   biv = (const float*)d_in[16];
        Wo  = (const float*)d_in[17];   bo  = (const float*)d_in[18];
        W_O = (const float*)d_in[19];
        W_val = (const float*)d_in[20]; b_val = (const float*)d_in[21];
        W_adv = (const float*)d_in[22]; b_adv = (const float*)d_in[23];
    } else {
        hid   = (const float*)d_in[0];  act  = (const float*)d_in[1];
        W_enc = (const float*)d_in[2];  b_enc = (const float*)d_in[3];
        Wq  = (const float*)d_in[4];    bq  = (const float*)d_in[5];
        Wk  = (const float*)d_in[6];    bk  = (const float*)d_in[7];
        Wv  = (const float*)d_in[8];    bv  = (const float*)d_in[9];
        Wiq = (const float*)d_in[10];   biq = (const float*)d_in[11];
        Wik = (const float*)d_in[12];   bik = (const float*)d_in[13];
        Wiv = (const float*)d_in[14];   biv = (const float*)d_in[15];
        Wo  = (const float*)d_in[16];   bo  = (const float*)d_in[17];
        W_O = (const float*)d_in[18];
        W_val = (const float*)d_in[19]; b_val = (const float*)d_in[20];
        W_adv = (const float*)d_in[21]; b_adv = (const float*)d_in[22];
        state = (const int*)  d_in[23];
    }

    fused_kernel<<<NB, 256>>>(hid, act, state, W_enc, b_enc,
                              Wq, bq, Wk, bk, Wv, bv,
                              Wiq, biq, Wik, bik, Wiv, biv,
                              Wo, bo, W_O, W_val, b_val, W_adv, b_adv,
                              (float*)d_out);
}